// round 14
// baseline (speedup 1.0000x reference)
#include <cuda_runtime.h>
#include <cuda_fp16.h>
#include <cstdint>

#define MAXQ 4096
#define TPB 256

// Packed per-query params
static __device__ float4 g_px[MAXQ];   // (c0, c1, c2, Ix as float bits) for x-stage
static __device__ int    g_Iy[MAXQ];
static __device__ float4 g_dy[MAXQ];   // (h0, h1, h2, h3*r) for y-stage

// Single-block precompute: both axes staged in smem once; thread t handles
// x-query t and y-query t. 1024 threads covers N<=1024 in one round.
__global__ __launch_bounds__(1024) void precompute_kernel(const float* __restrict__ xaxis,
                                                          const float* __restrict__ yaxis,
                                                          const float* __restrict__ xs,
                                                          const float* __restrict__ ys,
                                                          int N) {
    extern __shared__ float axs[];     // [0..N) = xaxis, [N..2N) = yaxis
    float* ay = axs + N;
    for (int i = threadIdx.x; i < N; i += blockDim.x) {
        axs[i] = xaxis[i];
        ay[i]  = yaxis[i];
    }
    __syncthreads();

    for (int q = threadIdx.x; q < N; q += blockDim.x) {
        // ---- x query ----
        {
            const float* ax = axs;
            float v = xs[q];
            int lo = 0, hi = N - 2;    // jnp.searchsorted(axis[1:-1], v, 'left')
            while (lo < hi) {
                int mid = (lo + hi) >> 1;
                if (ax[1 + mid] < v) lo = mid + 1; else hi = mid;
            }
            int I = lo;
            float x0 = ax[I], x1 = ax[I + 1], x2 = ax[I + 2];
            float dx = x1 - x0;
            float t = (v - x0) / dx;
            float t2 = t * t, t3 = t2 * t;
            float h0 = 1.0f - 3.0f * t2 + 2.0f * t3;
            float h1 = t - 2.0f * t2 + t3;
            float h2 = 3.0f * t2 - 2.0f * t3;
            float h3 = t3 - t2;
            float r = dx / (x2 - x1);
            g_px[q] = make_float4(h0 - h1, h1 + h2 - h3 * r, h3 * r, __int_as_float(I));
        }
        // ---- y query ----
        {
            const float* ax = ay;
            float v = ys[q];
            int lo = 0, hi = N - 2;
            while (lo < hi) {
                int mid = (lo + hi) >> 1;
                if (ax[1 + mid] < v) lo = mid + 1; else hi = mid;
            }
            int I = lo;
            float x0 = ax[I], x1 = ax[I + 1], x2 = ax[I + 2];
            float dx = x1 - x0;
            float t = (v - x0) / dx;
            float t2 = t * t, t3 = t2 * t;
            float h0 = 1.0f - 3.0f * t2 + 2.0f * t3;
            float h1 = t - 2.0f * t2 + t3;
            float h2 = 3.0f * t2 - 2.0f * t3;
            float h3 = t3 - t2;
            float r = dx / (x2 - x1);
            g_Iy[q] = I;
            g_dy[q] = make_float4(h0, h1, h2, h3 * r);
        }
    }
}

// 4-batch fused kernel (512 thr, ITERS=2), half4 gather array, with ALL
// global loads (a, b, s2) folded into the fill phase:
//   colt = d.y*(b-a) + d.w*(s2-b)   (fp32-exact column term, 8 regs live)
// Compute phase is then pure: params LDG.128 + 3 random LDS.64 + 4 STG —
// LDS-bound, overlapping with other resident blocks' LDG-bound fill phases.
template <int ITERS>
__global__ __launch_bounds__(512, 4) void fused4h_kernel(const float* __restrict__ signal,
                                                         float* __restrict__ out,
                                                         int N) {
    extern __shared__ uint2 w8[];      // N entries: (half2(w0,w1), half2(w2,w3))
    int bq = blockIdx.x / N;
    int qy = blockIdx.x - bq * N;
    int Iy = g_Iy[qy];
    float4 d = g_dy[qy];
    size_t pstride = (size_t)N * N;
    const float* __restrict__ rbase = signal + (size_t)(bq * 4) * pstride + (size_t)Iy * N;
    float* __restrict__ obase = out + (size_t)(bq * 4) * pstride + (size_t)qy * N;

    float colt[ITERS][4];

#pragma unroll
    for (int it = 0; it < ITERS; ++it) {
        int q = threadIdx.x + it * 512;
        float wv[4];
#pragma unroll
        for (int k = 0; k < 4; ++k) {
            const float* __restrict__ rk = rbase + (size_t)k * pstride;
            float a  = __ldg(rk + q);
            float b  = __ldg(rk + N + q);
            float s2 = __ldg(rk + 2 * N + q);
            colt[it][k] = d.y * (b - a) + d.w * (s2 - b);
            wv[k] = d.x * a + d.z * b;
        }
        __half2 h01 = __floats2half2_rn(wv[0], wv[1]);
        __half2 h23 = __floats2half2_rn(wv[2], wv[3]);
        w8[q] = make_uint2(*reinterpret_cast<uint32_t*>(&h01),
                           *reinterpret_cast<uint32_t*>(&h23));
    }
    __syncthreads();

#pragma unroll
    for (int it = 0; it < ITERS; ++it) {
        int q = threadIdx.x + it * 512;
        float4 p = g_px[q];
        int I = __float_as_int(p.w);
        uint2 ua = w8[I];
        uint2 ub = w8[I + 1];
        uint2 uc = w8[I + 2];
        float2 a01 = __half22float2(*reinterpret_cast<__half2*>(&ua.x));
        float2 a23 = __half22float2(*reinterpret_cast<__half2*>(&ua.y));
        float2 b01 = __half22float2(*reinterpret_cast<__half2*>(&ub.x));
        float2 b23 = __half22float2(*reinterpret_cast<__half2*>(&ub.y));
        float2 c01 = __half22float2(*reinterpret_cast<__half2*>(&uc.x));
        float2 c23 = __half22float2(*reinterpret_cast<__half2*>(&uc.y));
        obase[0 * pstride + q] = p.x * a01.x + p.y * b01.x + p.z * c01.x + colt[it][0];
        obase[1 * pstride + q] = p.x * a01.y + p.y * b01.y + p.z * c01.y + colt[it][1];
        obase[2 * pstride + q] = p.x * a23.x + p.y * b23.x + p.z * c23.x + colt[it][2];
        obase[3 * pstride + q] = p.x * a23.y + p.y * b23.y + p.z * c23.y + colt[it][3];
    }
}

// Generic single-batch fallback
__global__ __launch_bounds__(TPB) void fused_kernel_gen(const float* __restrict__ signal,
                                                        float* __restrict__ out,
                                                        int N) {
    extern __shared__ float w[];
    int b  = blockIdx.x / N;
    int qy = blockIdx.x - b * N;
    int Iy = g_Iy[qy];
    float4 d = g_dy[qy];
    size_t plane = (size_t)b * N * N;
    const float* __restrict__ r0 = signal + plane + (size_t)Iy * N;
    const float* __restrict__ r1 = r0 + N;
    const float* __restrict__ r2 = r1 + N;
    float* __restrict__ orow = out + plane + (size_t)qy * N;

    for (int q = threadIdx.x; q < N; q += TPB)
        w[q] = d.x * __ldg(r0 + q) + d.z * __ldg(r1 + q);
    __syncthreads();
    for (int q = threadIdx.x; q < N; q += TPB) {
        float4 p = g_px[q];
        int I = __float_as_int(p.w);
        float g = p.x * w[I] + p.y * w[I + 1] + p.z * w[I + 2];
        float a = __ldg(r0 + q), bb = __ldg(r1 + q), s2 = __ldg(r2 + q);
        orow[q] = g + d.y * (bb - a) + d.w * (s2 - bb);
    }
}

extern "C" void kernel_launch(void* const* d_in, const int* in_sizes, int n_in,
                              void* d_out, int out_size) {
    const float* xaxis  = (const float*)d_in[0];
    const float* yaxis  = (const float*)d_in[1];
    const float* signal = (const float*)d_in[2];
    const float* xs     = (const float*)d_in[3];
    const float* ys     = (const float*)d_in[4];
    float* out = (float*)d_out;

    int N = in_sizes[0];                       // 1024
    int B = (int)((long long)in_sizes[2] / ((long long)N * N));  // 32

    precompute_kernel<<<1, 1024, 2 * N * sizeof(float)>>>(xaxis, yaxis, xs, ys, N);

    if ((B % 4) == 0 && N == 1024) {
        fused4h_kernel<2><<<(B / 4) * N, 512, N * sizeof(uint2)>>>(signal, out, N);
    } else if ((B % 4) == 0 && N == 2048) {
        fused4h_kernel<4><<<(B / 4) * N, 512, N * sizeof(uint2)>>>(signal, out, N);
    } else if ((B % 4) == 0 && N == 512) {
        fused4h_kernel<1><<<(B / 4) * N, 512, N * sizeof(uint2)>>>(signal, out, N);
    } else {
        fused_kernel_gen<<<B * N, TPB, N * sizeof(float)>>>(signal, out, N);
    }
}

// round 15
// speedup vs baseline: 1.0663x; 1.0663x over previous
#include <cuda_runtime.h>
#include <cuda_fp16.h>
#include <cstdint>

#define MAXQ 4096
#define TPB 256

// Packed per-query params
static __device__ float4 g_px[MAXQ];   // (c0, c1, c2, Ix as float bits) for x-stage
static __device__ int    g_Iy[MAXQ];
static __device__ float4 g_dy[MAXQ];   // (h0, h1, h2, h3*r) for y-stage

// Multi-block precompute (R13-proven): axis staged in smem, binary search in smem.
__global__ void precompute_kernel(const float* __restrict__ xaxis,
                                  const float* __restrict__ yaxis,
                                  const float* __restrict__ xs,
                                  const float* __restrict__ ys,
                                  int N) {
    extern __shared__ float ax[];
    bool is_y = (blockIdx.y != 0);
    const float* axis = is_y ? yaxis : xaxis;
    const float* qs   = is_y ? ys    : xs;
    for (int i = threadIdx.x; i < N; i += blockDim.x)
        ax[i] = axis[i];
    __syncthreads();

    int q = blockIdx.x * blockDim.x + threadIdx.x;
    if (q >= N) return;
    float v = qs[q];
    // Exact replica of jnp.searchsorted(axis[1:-1], v, side='left')
    int lo = 0, hi = N - 2;
    while (lo < hi) {
        int mid = (lo + hi) >> 1;
        if (ax[1 + mid] < v) lo = mid + 1; else hi = mid;
    }
    int I = lo;
    float x0 = ax[I], x1 = ax[I + 1], x2 = ax[I + 2];
    float dx = x1 - x0;
    float t = (v - x0) / dx;
    float t2 = t * t, t3 = t2 * t;
    float h0 = 1.0f - 3.0f * t2 + 2.0f * t3;
    float h1 = t - 2.0f * t2 + t3;
    float h2 = 3.0f * t2 - 2.0f * t3;
    float h3 = t3 - t2;
    float r = dx / (x2 - x1);
    if (!is_y) {
        g_px[q] = make_float4(h0 - h1, h1 + h2 - h3 * r, h3 * r, __int_as_float(I));
    } else {
        g_Iy[q] = I;
        g_dy[q] = make_float4(h0, h1, h2, h3 * r);
    }
}

// 4-batch fused kernel, 512 thr, 2 iters, half4 gather array (uint2).
// All global loads (a,b,s2) folded into the fill; iter-0 params PREFETCHED
// into registers before the barrier (ptxas won't hoist LDG across BAR), and
// iter-1 params issued first thing after the barrier, so the compute phase
// starts with pure LDS work and the p1 load hides under iter-0's chain.
__global__ __launch_bounds__(512, 4) void fused4h_1k_kernel(const float* __restrict__ signal,
                                                            float* __restrict__ out,
                                                            int N) {
    extern __shared__ uint2 w8[];      // N entries: (half2(w0,w1), half2(w2,w3))
    int bq = blockIdx.x / N;
    int qy = blockIdx.x - bq * N;
    int Iy = g_Iy[qy];
    float4 d = g_dy[qy];
    size_t pstride = (size_t)N * N;
    const float* __restrict__ rbase = signal + (size_t)(bq * 4) * pstride + (size_t)Iy * N;
    float* __restrict__ obase = out + (size_t)(bq * 4) * pstride + (size_t)qy * N;

    int q0 = threadIdx.x;
    int q1 = threadIdx.x + 512;
    float colt0[4], colt1[4];

    // ---- fill: 24 LDGs, colt fp32-exact, w half4 ----
#pragma unroll
    for (int it = 0; it < 2; ++it) {
        int q = (it == 0) ? q0 : q1;
        float* colt = (it == 0) ? colt0 : colt1;
        float wv[4];
#pragma unroll
        for (int k = 0; k < 4; ++k) {
            const float* __restrict__ rk = rbase + (size_t)k * pstride;
            float a  = __ldg(rk + q);
            float b  = __ldg(rk + N + q);
            float s2 = __ldg(rk + 2 * N + q);
            colt[k] = d.y * (b - a) + d.w * (s2 - b);
            wv[k] = d.x * a + d.z * b;
        }
        __half2 h01 = __floats2half2_rn(wv[0], wv[1]);
        __half2 h23 = __floats2half2_rn(wv[2], wv[3]);
        w8[q] = make_uint2(*reinterpret_cast<uint32_t*>(&h01),
                           *reinterpret_cast<uint32_t*>(&h23));
    }

    // prefetch iter-0 params across the barrier (+4 regs)
    float4 p0 = g_px[q0];
    __syncthreads();

    // issue iter-1 params immediately; overlaps iter-0's LDS/FMA chain
    float4 p1 = g_px[q1];

    // ---- compute iter 0 (params already resident) ----
    {
        int I = __float_as_int(p0.w);
        uint2 ua = w8[I];
        uint2 ub = w8[I + 1];
        uint2 uc = w8[I + 2];
        float2 a01 = __half22float2(*reinterpret_cast<__half2*>(&ua.x));
        float2 a23 = __half22float2(*reinterpret_cast<__half2*>(&ua.y));
        float2 b01 = __half22float2(*reinterpret_cast<__half2*>(&ub.x));
        float2 b23 = __half22float2(*reinterpret_cast<__half2*>(&ub.y));
        float2 c01 = __half22float2(*reinterpret_cast<__half2*>(&uc.x));
        float2 c23 = __half22float2(*reinterpret_cast<__half2*>(&uc.y));
        obase[0 * pstride + q0] = p0.x * a01.x + p0.y * b01.x + p0.z * c01.x + colt0[0];
        obase[1 * pstride + q0] = p0.x * a01.y + p0.y * b01.y + p0.z * c01.y + colt0[1];
        obase[2 * pstride + q0] = p0.x * a23.x + p0.y * b23.x + p0.z * c23.x + colt0[2];
        obase[3 * pstride + q0] = p0.x * a23.y + p0.y * b23.y + p0.z * c23.y + colt0[3];
    }
    // ---- compute iter 1 ----
    {
        int I = __float_as_int(p1.w);
        uint2 ua = w8[I];
        uint2 ub = w8[I + 1];
        uint2 uc = w8[I + 2];
        float2 a01 = __half22float2(*reinterpret_cast<__half2*>(&ua.x));
        float2 a23 = __half22float2(*reinterpret_cast<__half2*>(&ua.y));
        float2 b01 = __half22float2(*reinterpret_cast<__half2*>(&ub.x));
        float2 b23 = __half22float2(*reinterpret_cast<__half2*>(&ub.y));
        float2 c01 = __half22float2(*reinterpret_cast<__half2*>(&uc.x));
        float2 c23 = __half22float2(*reinterpret_cast<__half2*>(&uc.y));
        obase[0 * pstride + q1] = p1.x * a01.x + p1.y * b01.x + p1.z * c01.x + colt1[0];
        obase[1 * pstride + q1] = p1.x * a01.y + p1.y * b01.y + p1.z * c01.y + colt1[1];
        obase[2 * pstride + q1] = p1.x * a23.x + p1.y * b23.x + p1.z * c23.x + colt1[2];
        obase[3 * pstride + q1] = p1.x * a23.y + p1.y * b23.y + p1.z * c23.y + colt1[3];
    }
}

// Generic single-batch fallback
__global__ __launch_bounds__(TPB) void fused_kernel_gen(const float* __restrict__ signal,
                                                        float* __restrict__ out,
                                                        int N) {
    extern __shared__ float w[];
    int b  = blockIdx.x / N;
    int qy = blockIdx.x - b * N;
    int Iy = g_Iy[qy];
    float4 d = g_dy[qy];
    size_t plane = (size_t)b * N * N;
    const float* __restrict__ r0 = signal + plane + (size_t)Iy * N;
    const float* __restrict__ r1 = r0 + N;
    const float* __restrict__ r2 = r1 + N;
    float* __restrict__ orow = out + plane + (size_t)qy * N;

    for (int q = threadIdx.x; q < N; q += TPB)
        w[q] = d.x * __ldg(r0 + q) + d.z * __ldg(r1 + q);
    __syncthreads();
    for (int q = threadIdx.x; q < N; q += TPB) {
        float4 p = g_px[q];
        int I = __float_as_int(p.w);
        float g = p.x * w[I] + p.y * w[I + 1] + p.z * w[I + 2];
        float a = __ldg(r0 + q), bb = __ldg(r1 + q), s2 = __ldg(r2 + q);
        orow[q] = g + d.y * (bb - a) + d.w * (s2 - bb);
    }
}

extern "C" void kernel_launch(void* const* d_in, const int* in_sizes, int n_in,
                              void* d_out, int out_size) {
    const float* xaxis  = (const float*)d_in[0];
    const float* yaxis  = (const float*)d_in[1];
    const float* signal = (const float*)d_in[2];
    const float* xs     = (const float*)d_in[3];
    const float* ys     = (const float*)d_in[4];
    float* out = (float*)d_out;

    int N = in_sizes[0];                       // 1024
    int B = (int)((long long)in_sizes[2] / ((long long)N * N));  // 32

    dim3 pg((N + TPB - 1) / TPB, 2);
    precompute_kernel<<<pg, TPB, N * sizeof(float)>>>(xaxis, yaxis, xs, ys, N);

    if ((B % 4) == 0 && N == 1024) {
        fused4h_1k_kernel<<<(B / 4) * N, 512, N * sizeof(uint2)>>>(signal, out, N);
    } else {
        fused_kernel_gen<<<B * N, TPB, N * sizeof(float)>>>(signal, out, N);
    }
}